// round 7
// baseline (speedup 1.0000x reference)
#include <cuda_runtime.h>

#define DEG 32
#define D 128
#define NEG_SLOPE 0.01f

// Warp-per-node, barrier-free. Each warp loads full 512B rows per instruction.
__global__ __launch_bounds__(128, 8)
void gat_reduce_kernel(const float* __restrict__ a1,
                       const float* __restrict__ a2,
                       const float* __restrict__ ft,
                       float* __restrict__ out,
                       int N)
{
    const int warp = threadIdx.x >> 5;   // 0..3
    const int lane = threadIdx.x & 31;
    const int n = blockIdx.x * 4 + warp;
    if (n >= N) return;

    const size_t base = (size_t)n * DEG * D;
    const float4* a2v = reinterpret_cast<const float4*>(a2 + base);
    const float4* ftv = reinterpret_cast<const float4*>(ft + base);
    const float4* a1v = reinterpret_cast<const float4*>(a1 + (size_t)n * D);
    float4*       ov  = reinterpret_cast<float4*>(out + (size_t)n * D);

    // ---- a1 row sum: 32 float4 = one warp load ----
    float4 av = __ldcs(&a1v[lane]);
    float S1 = (av.x + av.y) + (av.z + av.w);
    #pragma unroll
    for (int o = 16; o; o >>= 1) S1 += __shfl_xor_sync(0xFFFFFFFFu, S1, o);

    // ---- per-neighbor logit sums; lane g ends up holding logit[g] ----
    // Row g = a2v[g*32 .. g*32+31]; one warp-load per row, batched 8-deep.
    float logit = 0.0f;
    #pragma unroll
    for (int b = 0; b < 4; b++) {
        float4 x[8];
        #pragma unroll
        for (int i = 0; i < 8; i++)
            x[i] = __ldcs(&a2v[(b * 8 + i) * (D / 4) + lane]);
        #pragma unroll
        for (int i = 0; i < 8; i++) {
            float s = (x[i].x + x[i].y) + (x[i].z + x[i].w);
            #pragma unroll
            for (int o = 16; o; o >>= 1) s += __shfl_xor_sync(0xFFFFFFFFu, s, o);
            if (lane == b * 8 + i) logit = s;
        }
    }

    // ---- softmax over 32 neighbors, entirely in-warp (lane = g) ----
    float a = logit + S1;
    a = (a > 0.0f) ? a : NEG_SLOPE * a;                   // leaky relu
    float m = a;
    #pragma unroll
    for (int o = 16; o; o >>= 1) m = fmaxf(m, __shfl_xor_sync(0xFFFFFFFFu, m, o));
    float e = __expf(a - m);
    float sum = e;
    #pragma unroll
    for (int o = 16; o; o >>= 1) sum += __shfl_xor_sync(0xFFFFFFFFu, sum, o);
    const float e_norm = e / sum;

    // ---- weighted accumulation: full rows again, weights via shuffle ----
    float4 acc = make_float4(0.f, 0.f, 0.f, 0.f);
    #pragma unroll
    for (int b = 0; b < 4; b++) {
        float4 f[8];
        #pragma unroll
        for (int i = 0; i < 8; i++)
            f[i] = __ldcs(&ftv[(b * 8 + i) * (D / 4) + lane]);
        #pragma unroll
        for (int i = 0; i < 8; i++) {
            float w = __shfl_sync(0xFFFFFFFFu, e_norm, b * 8 + i);
            acc.x += w * f[i].x;
            acc.y += w * f[i].y;
            acc.z += w * f[i].z;
            acc.w += w * f[i].w;
        }
    }

    // ---- store: 32 float4 = 512B contiguous per warp ----
    __stcs(&ov[lane], acc);
}

extern "C" void kernel_launch(void* const* d_in, const int* in_sizes, int n_in,
                              void* d_out, int out_size)
{
    const float* a1 = (const float*)d_in[0];   // [N, D]
    const float* a2 = (const float*)d_in[1];   // [N, DEG, D]
    const float* ft = (const float*)d_in[2];   // [N, DEG, D]
    float* out = (float*)d_out;                // [N, D]

    int N = in_sizes[0] / D;
    int blocks = (N + 3) / 4;                  // 4 nodes (warps) per CTA
    gat_reduce_kernel<<<blocks, 128>>>(a1, a2, ft, out, N);
}